// round 1
// baseline (speedup 1.0000x reference)
#include <cuda_runtime.h>
#include <cstdint>

#define PL1 20
#define PR1 70
#define PL2 120
#define PR2 170
#define NFACT 10
#define TT 200
#define NTRIALS 256
#define NCONFIGS 128
#define TW 50
#define NOFF (2 * NFACT)

// Device-global scratch (no allocations allowed)
__device__ float  g_factors[NFACT * TT];
__device__ float2 g_pairs[NFACT * TT];   // (f[i], f[i+1])
__device__ float  g_peak[NOFF];          // avg_peak (concat p1, p2)
__device__ float  g_bnd[5];              // tL1, tR1, tL2, tR2, dt

// ---------------------------------------------------------------------------
// Kernel 1: softplus, pair table, argmax peaks, boundaries. One block.
// ---------------------------------------------------------------------------
__global__ void prep_kernel(const float* __restrict__ beta,
                            const float* __restrict__ time) {
    int tid = threadIdx.x;
    for (int i = tid; i < NFACT * TT; i += blockDim.x) {
        float x = beta[i];
        // jax.nn.softplus: max(x,0) + log1p(exp(-|x|))
        g_factors[i] = fmaxf(x, 0.0f) + log1pf(expf(-fabsf(x)));
    }
    __syncthreads();
    for (int i = tid; i < NFACT * TT; i += blockDim.x) {
        int col = i % TT;
        float a = g_factors[i];
        float b = (col < TT - 1) ? g_factors[i + 1] : a;
        g_pairs[i] = make_float2(a, b);
    }
    if (tid < NOFF) {
        int side = tid / NFACT;
        int f    = tid % NFACT;
        int lo = side ? PL2 : PL1;
        int hi = side ? PR2 : PR1;
        float best = -3.402823466e+38f;
        int   bi   = lo;
        for (int i = lo; i < hi; ++i) {
            float v = g_factors[f * TT + i];
            if (v > best) { best = v; bi = i; }   // first max, like jnp.argmax
        }
        g_peak[tid] = time[bi];
    }
    if (tid == 0) {
        g_bnd[0] = time[PL1];
        g_bnd[1] = time[PR1];
        g_bnd[2] = time[PL2];
        g_bnd[3] = time[PR2];
        g_bnd[4] = time[1] - time[0];
    }
}

// ---------------------------------------------------------------------------
// Kernel 2: broadcast fill of the 100 non-warped time columns per factor.
// Each block handles one (f, tt) row = 32768 contiguous floats.
// ---------------------------------------------------------------------------
__global__ void bcast_kernel(float* __restrict__ out) {
    int row = blockIdx.x;            // 0..999
    int f   = row / 100;
    int r   = row % 100;
    int tt;
    if (r < PL1)                tt = r;               // [0,20)
    else if (r < PL1 + (PL2 - PR1)) tt = r + (PR1 - PL1); // [70,120)
    else                        tt = r + (PR1 - PL1) + (PR2 - PL2); // [170,200)

    float v = g_factors[f * TT + tt];
    float4 v4 = make_float4(v, v, v, v);
    float4* base = reinterpret_cast<float4*>(
        out + ((size_t)f * TT + tt) * (NTRIALS * NCONFIGS));
    const int nvec = (NTRIALS * NCONFIGS) / 4;   // 8192
    for (int i = threadIdx.x; i < nvec; i += blockDim.x)
        base[i] = v4;
}

// ---------------------------------------------------------------------------
// Kernel 3: warped windows.
// grid = (NTRIALS, 20): block (t, j) where j = side*10 + f.
// 64 threads: 2 warps split the 50 tw steps; each lane owns 4 configs
// -> STG.128 stores, fully coalesced.
// ---------------------------------------------------------------------------
__global__ void __launch_bounds__(64) warp_kernel(
    const float* __restrict__ trial_off,   // (NTRIALS, NCONFIGS, 20)
    const float* __restrict__ cfg_off,     // (NCONFIGS, 20)
    float* __restrict__ out) {

    const int t    = blockIdx.x;
    const int j    = blockIdx.y;          // 0..19
    const int side = j / NFACT;
    const int f    = j % NFACT;

    const float tl = g_bnd[side * 2];
    const float tr = g_bnd[side * 2 + 1];
    const float dt = g_bnd[4];
    const float pk = g_peak[j];
    const int baseT = side ? PL2 : PL1;

    // Pair segment for this factor row, indices baseT..baseT+50
    __shared__ float2 s_pairs[TW + 1];    // 51
    const int tid = threadIdx.x;
    for (int i = tid; i <= TW; i += blockDim.x)
        s_pairs[i] = g_pairs[f * TT + baseT + i];
    __syncthreads();

    const int lane = tid & 31;
    const int w    = tid >> 5;            // 0 or 1
    const int c0   = lane * 4;

    float lsp[4], lslope[4], rslope[4];
#pragma unroll
    for (int q = 0; q < 4; ++q) {
        int c = c0 + q;
        float off = trial_off[((size_t)t * NCONFIGS + c) * NOFF + j]
                  + cfg_off[c * NOFF + j];
        float sn = pk + off;
        if (sn <= tl) sn = tl + dt;
        if (sn >= tr) sn = tr - dt;
        lsp[q]    = sn - tl;
        lslope[q] = (pk - tl) / lsp[q];
        rslope[q] = (pk - tr) / (sn - tr);
    }

    const int twlo = w * (TW / 2);
    const int twhi = twlo + (TW / 2);
    for (int tw = twlo; tw < twhi; ++tw) {
        float lst = (float)tw * dt;
        float4 v;
        float* vp = &v.x;
#pragma unroll
        for (int q = 0; q < 4; ++q) {
            float wt = (lst < lsp[q]) ? lst * lslope[q] + tl
                                      : (lst - lsp[q]) * rslope[q] + pk;
            float wi = wt / dt;                  // true division: exact at edges
            float fl = floorf(wi);
            float cw = wi - fl;
            int   fi = (int)fl - baseT;
            fi = max(0, min(fi, TW));            // defensive clamp into [0,50]
            float2 p = s_pairs[fi];
            vp[q] = (1.0f - cw) * p.x + cw * p.y;
        }
        size_t oidx = (((size_t)f * TT + baseT + tw) * NTRIALS + t) * NCONFIGS + c0;
        *reinterpret_cast<float4*>(out + oidx) = v;
    }
}

// ---------------------------------------------------------------------------
extern "C" void kernel_launch(void* const* d_in, const int* in_sizes, int n_in,
                              void* d_out, int out_size) {
    const float* beta  = (const float*)d_in[0];   // (10, 200)
    const float* trial = (const float*)d_in[1];   // (1, 256, 128, 20)
    const float* cfg   = (const float*)d_in[2];   // (1, 128, 20)
    const float* time  = (const float*)d_in[3];   // (200,)
    float* out = (float*)d_out;                   // (10,200,1,1,256,128)

    prep_kernel<<<1, 256>>>(beta, time);
    bcast_kernel<<<NFACT * 100, 256>>>(out);
    warp_kernel<<<dim3(NTRIALS, NOFF), 64>>>(trial, cfg, out);
}

// round 6
// speedup vs baseline: 1.3711x; 1.3711x over previous
#include <cuda_runtime.h>
#include <cstdint>

#define PL1 20
#define PR1 70
#define PL2 120
#define PR2 170
#define NFACT 10
#define TT 200
#define NTRIALS 256
#define NCONFIGS 128
#define TW 50
#define NOFF (2 * NFACT)

#define N_WARP_BLOCKS (NTRIALS * NOFF)            // 5120
#define BCAST_ROWS (NFACT * 100)                  // 1000
#define BCAST_PARTS 4                             // 8192 floats per part
#define N_BCAST_BLOCKS (BCAST_ROWS * BCAST_PARTS) // 4000

__device__ __forceinline__ float softplus_f(float x) {
    // jax.nn.softplus: max(x,0) + log1p(exp(-|x|))
    return fmaxf(x, 0.0f) + log1pf(expf(-fabsf(x)));
}

// ---------------------------------------------------------------------------
// One fused kernel, one wave. blockIdx.x < 5120 -> warped-window role,
// else -> broadcast-fill role. 64 threads per block.
// ---------------------------------------------------------------------------
__global__ void __launch_bounds__(64) fused_kernel(
    const float* __restrict__ beta,        // (10, 200)
    const float* __restrict__ trial_off,   // (256, 128, 20)
    const float* __restrict__ cfg_off,     // (128, 20)
    const float* __restrict__ time,        // (200,)
    float* __restrict__ out) {             // (10, 200, 256, 128)

    const int bid = blockIdx.x;
    const int tid = threadIdx.x;

    if (bid >= N_WARP_BLOCKS) {
        // ------------------- broadcast role -------------------
        int b    = bid - N_WARP_BLOCKS;
        int row  = b >> 2;                 // 0..999
        int part = b & 3;
        int f    = row / 100;
        int r    = row % 100;
        int tt;
        if (r < PL1)                        tt = r;          // [0,20)
        else if (r < PL1 + (PL2 - PR1))     tt = r + (PR1 - PL1);             // [70,120)
        else                                tt = r + (PR1 - PL1) + (PR2 - PL2); // [170,200)

        float v = softplus_f(beta[f * TT + tt]);
        float4 v4 = make_float4(v, v, v, v);
        float4* base = reinterpret_cast<float4*>(
            out + ((size_t)f * TT + tt) * (NTRIALS * NCONFIGS)) + part * 2048;
#pragma unroll 4
        for (int i = tid; i < 2048; i += 64)
            __stcs(base + i, v4);
        return;
    }

    // ------------------- warped-window role -------------------
    // j = side*10 + f, t = trial. Consecutive bids share j -> adjacent stores.
    const int j    = bid / NTRIALS;        // 0..19
    const int t    = bid % NTRIALS;
    const int side = j / NFACT;
    const int f    = j % NFACT;
    const int baseT = side ? PL2 : PL1;

    __shared__ float  s_f[TW + 2];         // softplus(beta[f, baseT .. baseT+51])
    __shared__ float2 s_pairs[TW + 1];     // (s_f[i], s_f[i+1])
    __shared__ float  s_pk;

    if (tid < TW + 2)
        s_f[tid] = softplus_f(beta[f * TT + baseT + tid]);
    __syncthreads();

    // first-max argmax over s_f[0..49] (matches jnp.argmax on factors; softplus
    // values themselves are compared, so the tie rule is identical)
    if (tid < 32) {
        float v = (tid < TW) ? s_f[tid] : -3.402823466e+38f;
        int   idx = tid;
        int   i2  = tid + 32;
        if (i2 < TW) {
            float v2 = s_f[i2];
            if (v2 > v) { v = v2; idx = i2; }
        }
#pragma unroll
        for (int d = 16; d; d >>= 1) {
            float ov = __shfl_down_sync(0xffffffffu, v, d);
            int   oi = __shfl_down_sync(0xffffffffu, idx, d);
            if (ov > v || (ov == v && oi < idx)) { v = ov; idx = oi; }
        }
        if (tid == 0) s_pk = time[baseT + idx];
    }
    if (tid <= TW)
        s_pairs[tid] = make_float2(s_f[tid], s_f[tid + 1]);
    __syncthreads();

    const float tl = time[baseT];
    const float tr = time[baseT + TW];
    const float dt = time[1] - time[0];
    const float inv_dt = 1.0f / dt;
    const float pk = s_pk;

    const int lane = tid & 31;
    const int w    = tid >> 5;             // 0 or 1
    const int c0   = lane * 4;

    float lsp[4], lslope[4], rslope[4];
#pragma unroll
    for (int q = 0; q < 4; ++q) {
        int c = c0 + q;
        float off = trial_off[((size_t)t * NCONFIGS + c) * NOFF + j]
                  + cfg_off[c * NOFF + j];
        float sn = pk + off;
        if (sn <= tl) sn = tl + dt;
        if (sn >= tr) sn = tr - dt;
        lsp[q]    = sn - tl;
        lslope[q] = (pk - tl) / lsp[q];
        rslope[q] = (pk - tr) / (sn - tr);
    }

    const float wlo = (float)baseT;
    const float whi = (float)(baseT + TW);

    const int twlo = w * (TW / 2);
    const int twhi = twlo + (TW / 2);
    for (int tw = twlo; tw < twhi; ++tw) {
        float lst = (float)tw * dt;
        float4 v;
        float* vp = &v.x;
#pragma unroll
        for (int q = 0; q < 4; ++q) {
            float wt = (lst < lsp[q]) ? fmaf(lst, lslope[q], tl)
                                      : fmaf(lst - lsp[q], rslope[q], pk);
            float wi = wt * inv_dt;
            // clamp BEFORE floor so (fi, cw) stay consistent at window edges
            wi = fminf(fmaxf(wi, wlo), whi);
            float fl = floorf(wi);
            float cw = wi - fl;
            int   fi = (int)fl - baseT;    // guaranteed in [0, TW]
            float2 p = s_pairs[fi];
            vp[q] = fmaf(cw, p.y - p.x, p.x);
        }
        size_t oidx = (((size_t)f * TT + baseT + tw) * NTRIALS + t) * NCONFIGS + c0;
        __stcs(reinterpret_cast<float4*>(out + oidx), v);
    }
}

// ---------------------------------------------------------------------------
extern "C" void kernel_launch(void* const* d_in, const int* in_sizes, int n_in,
                              void* d_out, int out_size) {
    const float* beta  = (const float*)d_in[0];   // (10, 200)
    const float* trial = (const float*)d_in[1];   // (1, 256, 128, 20)
    const float* cfg   = (const float*)d_in[2];   // (1, 128, 20)
    const float* time  = (const float*)d_in[3];   // (200,)
    float* out = (float*)d_out;                   // (10,200,1,1,256,128)

    fused_kernel<<<N_WARP_BLOCKS + N_BCAST_BLOCKS, 64>>>(beta, trial, cfg, time, out);
}